// round 1
// baseline (speedup 1.0000x reference)
#include <cuda_runtime.h>
#include <cuda_bf16.h>

#define N_NODES 100000
#define N_EDGES 1600000
#define F 64
#define NCLS 16
#define NEG_SLOPE 0.01f

#define SCAN_BLK 1024
#define SCAN_NB ((N_NODES + SCAN_BLK - 1) / SCAN_BLK)   // 98

// ---------------- scratch (device globals; no runtime allocation) ------------
__device__ int   g_off[N_NODES + 1];
__device__ int   g_cursor[N_NODES];
__device__ int   g_csr[N_EDGES];
__device__ int   g_bsum[SCAN_NB];
__device__ float g_P[(size_t)N_NODES * F];
__device__ float g_pooled[(size_t)N_NODES * F];
__device__ float g_H[(size_t)N_NODES * F];

// ---------------- CSR build --------------------------------------------------
__global__ void zero_deg_kernel() {
    int i = blockIdx.x * blockDim.x + threadIdx.x;
    if (i <= N_NODES) g_off[i] = 0;
}

__global__ void hist_kernel(const int* __restrict__ dst) {
    int e = blockIdx.x * blockDim.x + threadIdx.x;
    if (e < N_EDGES) atomicAdd(&g_off[dst[e]], 1);
}

__global__ __launch_bounds__(SCAN_BLK) void scan1_kernel() {
    __shared__ int s[SCAN_BLK];
    int t = threadIdx.x;
    int idx = blockIdx.x * SCAN_BLK + t;
    int val = (idx < N_NODES) ? g_off[idx] : 0;
    s[t] = val;
    __syncthreads();
    #pragma unroll
    for (int o = 1; o < SCAN_BLK; o <<= 1) {
        int x = (t >= o) ? s[t - o] : 0;
        __syncthreads();
        s[t] += x;
        __syncthreads();
    }
    if (idx < N_NODES) g_off[idx] = s[t] - val;   // exclusive within block
    if (t == SCAN_BLK - 1) g_bsum[blockIdx.x] = s[t];
}

__global__ void scan2_kernel() {
    // single thread: scan 98 block sums
    int carry = 0;
    for (int b = 0; b < SCAN_NB; b++) {
        int v = g_bsum[b];
        g_bsum[b] = carry;
        carry += v;
    }
    g_off[N_NODES] = carry;   // == N_EDGES
}

__global__ void scan3_kernel() {
    int i = blockIdx.x * blockDim.x + threadIdx.x;
    if (i < N_NODES) {
        int o = g_off[i] + g_bsum[i / SCAN_BLK];
        g_off[i] = o;
        g_cursor[i] = o;
    }
}

__global__ void fill_csr_kernel(const int* __restrict__ src,
                                const int* __restrict__ dst) {
    int e = blockIdx.x * blockDim.x + threadIdx.x;
    if (e < N_EDGES) {
        int pos = atomicAdd(&g_cursor[dst[e]], 1);
        g_csr[pos] = src[e];
    }
}

// ---------------- GEMM: Y[N,64] = relu(X[N,64] @ W[64,64] + b) ---------------
__global__ __launch_bounds__(256) void gemm_pool_kernel(
        const float* __restrict__ X, const float* __restrict__ W,
        const float* __restrict__ b, float* __restrict__ Y) {
    __shared__ float4 sW[F * F / 4];
    __shared__ float  sb[F];
    int t = threadIdx.x;
    const float4* W4 = (const float4*)W;
    #pragma unroll
    for (int i = 0; i < F * F / 4; i += 256) sW[i + t] = W4[i + t];
    if (t < F) sb[t] = b[t];
    __syncthreads();

    int r = blockIdx.x * 256 + t;
    if (r >= N_NODES) return;

    float acc[F];
    #pragma unroll
    for (int j = 0; j < F; j++) acc[j] = sb[j];

    const float4* xr = (const float4*)(X + (size_t)r * F);
    #pragma unroll
    for (int k4 = 0; k4 < F / 4; k4++) {
        float4 xv = __ldg(&xr[k4]);
        float xs[4] = {xv.x, xv.y, xv.z, xv.w};
        #pragma unroll
        for (int kk = 0; kk < 4; kk++) {
            int k = k4 * 4 + kk;
            #pragma unroll
            for (int j4 = 0; j4 < F / 4; j4++) {
                float4 w = sW[k * (F / 4) + j4];
                acc[j4 * 4 + 0] += xs[kk] * w.x;
                acc[j4 * 4 + 1] += xs[kk] * w.y;
                acc[j4 * 4 + 2] += xs[kk] * w.z;
                acc[j4 * 4 + 3] += xs[kk] * w.w;
            }
        }
    }
    float4* yr = (float4*)(Y + (size_t)r * F);
    #pragma unroll
    for (int j4 = 0; j4 < F / 4; j4++) {
        float4 o;
        o.x = fmaxf(acc[j4 * 4 + 0], 0.f);
        o.y = fmaxf(acc[j4 * 4 + 1], 0.f);
        o.z = fmaxf(acc[j4 * 4 + 2], 0.f);
        o.w = fmaxf(acc[j4 * 4 + 3], 0.f);
        yr[j4] = o;
    }
}

// ---------------- segment max pool: warp per dst node ------------------------
__global__ __launch_bounds__(256) void pool_kernel(const float* __restrict__ P,
                                                   float* __restrict__ Pl) {
    int gwarp = (blockIdx.x * 256 + threadIdx.x) >> 5;
    int lane  = threadIdx.x & 31;
    if (gwarp >= N_NODES) return;
    int s0 = g_off[gwarp];
    int s1 = g_off[gwarp + 1];
    float m0 = 0.f, m1 = 0.f;
    int e = s0;
    for (; e + 4 <= s1; e += 4) {
        int i0 = g_csr[e + 0], i1 = g_csr[e + 1];
        int i2 = g_csr[e + 2], i3 = g_csr[e + 3];
        float a0 = P[i0 * F + lane],      b0 = P[i0 * F + 32 + lane];
        float a1 = P[i1 * F + lane],      b1 = P[i1 * F + 32 + lane];
        float a2 = P[i2 * F + lane],      b2 = P[i2 * F + 32 + lane];
        float a3 = P[i3 * F + lane],      b3 = P[i3 * F + 32 + lane];
        m0 = fmaxf(m0, fmaxf(fmaxf(a0, a1), fmaxf(a2, a3)));
        m1 = fmaxf(m1, fmaxf(fmaxf(b0, b1), fmaxf(b2, b3)));
    }
    for (; e < s1; e++) {
        int i = g_csr[e];
        m0 = fmaxf(m0, P[i * F + lane]);
        m1 = fmaxf(m1, P[i * F + 32 + lane]);
    }
    Pl[gwarp * F + lane]      = m0;
    Pl[gwarp * F + 32 + lane] = m1;
}

// ------- GEMM: Y[N,DOUT] = act(X@Ws + PL@Wn + b), K=64 each, act per ACT -----
// ACT: 0 = none, 1 = leaky_relu
template <int DOUT, int ACT>
__global__ __launch_bounds__(256) void gemm_out_kernel(
        const float* __restrict__ X, const float* __restrict__ PL,
        const float* __restrict__ Ws, const float* __restrict__ Wn,
        const float* __restrict__ b, float* __restrict__ Y) {
    __shared__ float4 sWs[F * DOUT / 4];
    __shared__ float4 sWn[F * DOUT / 4];
    __shared__ float  sb[DOUT];
    int t = threadIdx.x;
    const float4* Ws4 = (const float4*)Ws;
    const float4* Wn4 = (const float4*)Wn;
    for (int i = t; i < F * DOUT / 4; i += 256) { sWs[i] = Ws4[i]; sWn[i] = Wn4[i]; }
    if (t < DOUT) sb[t] = b[t];
    __syncthreads();

    int r = blockIdx.x * 256 + t;
    if (r >= N_NODES) return;

    float acc[DOUT];
    #pragma unroll
    for (int j = 0; j < DOUT; j++) acc[j] = sb[j];

    const float4* xr = (const float4*)(X + (size_t)r * F);
    #pragma unroll
    for (int k4 = 0; k4 < F / 4; k4++) {
        float4 xv = __ldg(&xr[k4]);
        float xs[4] = {xv.x, xv.y, xv.z, xv.w};
        #pragma unroll
        for (int kk = 0; kk < 4; kk++) {
            int k = k4 * 4 + kk;
            #pragma unroll
            for (int j4 = 0; j4 < DOUT / 4; j4++) {
                float4 w = sWs[k * (DOUT / 4) + j4];
                acc[j4 * 4 + 0] += xs[kk] * w.x;
                acc[j4 * 4 + 1] += xs[kk] * w.y;
                acc[j4 * 4 + 2] += xs[kk] * w.z;
                acc[j4 * 4 + 3] += xs[kk] * w.w;
            }
        }
    }
    const float4* pr = (const float4*)(PL + (size_t)r * F);
    #pragma unroll
    for (int k4 = 0; k4 < F / 4; k4++) {
        float4 xv = __ldg(&pr[k4]);
        float xs[4] = {xv.x, xv.y, xv.z, xv.w};
        #pragma unroll
        for (int kk = 0; kk < 4; kk++) {
            int k = k4 * 4 + kk;
            #pragma unroll
            for (int j4 = 0; j4 < DOUT / 4; j4++) {
                float4 w = sWn[k * (DOUT / 4) + j4];
                acc[j4 * 4 + 0] += xs[kk] * w.x;
                acc[j4 * 4 + 1] += xs[kk] * w.y;
                acc[j4 * 4 + 2] += xs[kk] * w.z;
                acc[j4 * 4 + 3] += xs[kk] * w.w;
            }
        }
    }
    float4* yr = (float4*)(Y + (size_t)r * DOUT);
    #pragma unroll
    for (int j4 = 0; j4 < DOUT / 4; j4++) {
        float4 o;
        float v0 = acc[j4 * 4 + 0], v1 = acc[j4 * 4 + 1];
        float v2 = acc[j4 * 4 + 2], v3 = acc[j4 * 4 + 3];
        if (ACT == 1) {
            v0 = (v0 >= 0.f) ? v0 : NEG_SLOPE * v0;
            v1 = (v1 >= 0.f) ? v1 : NEG_SLOPE * v1;
            v2 = (v2 >= 0.f) ? v2 : NEG_SLOPE * v2;
            v3 = (v3 >= 0.f) ? v3 : NEG_SLOPE * v3;
        }
        o.x = v0; o.y = v1; o.z = v2; o.w = v3;
        yr[j4] = o;
    }
}

// ---------------- launch -----------------------------------------------------
extern "C" void kernel_launch(void* const* d_in, const int* in_sizes, int n_in,
                              void* d_out, int out_size) {
    const float* in_feat = (const float*)d_in[0];
    const int*   src     = (const int*)d_in[1];
    const int*   dst     = (const int*)d_in[2];
    const float* W_pool1 = (const float*)d_in[3];
    const float* b_pool1 = (const float*)d_in[4];
    const float* W_self1 = (const float*)d_in[5];
    const float* W_neigh1= (const float*)d_in[6];
    const float* bias1   = (const float*)d_in[7];
    const float* W_pool2 = (const float*)d_in[8];
    const float* b_pool2 = (const float*)d_in[9];
    const float* W_self2 = (const float*)d_in[10];
    const float* W_neigh2= (const float*)d_in[11];
    const float* bias2   = (const float*)d_in[12];
    float* out = (float*)d_out;

    // device symbol addresses (queries only; no allocation)
    float *dP, *dPl, *dH;
    cudaGetSymbolAddress((void**)&dP, g_P);
    cudaGetSymbolAddress((void**)&dPl, g_pooled);
    cudaGetSymbolAddress((void**)&dH, g_H);

    const int EB = (N_EDGES + 255) / 256;
    const int NB256 = (N_NODES + 255) / 256;
    const int GEMMB = (N_NODES + 255) / 256;
    const int POOLB = (N_NODES * 32 + 255) / 256;

    // ---- CSR build (per call; deterministic) ----
    zero_deg_kernel<<<(N_NODES + 1 + 255) / 256, 256>>>();
    hist_kernel<<<EB, 256>>>(dst);
    scan1_kernel<<<SCAN_NB, SCAN_BLK>>>();
    scan2_kernel<<<1, 1>>>();
    scan3_kernel<<<NB256, 256>>>();
    fill_csr_kernel<<<EB, 256>>>(src, dst);

    // ---- layer 1 ----
    gemm_pool_kernel<<<GEMMB, 256>>>(in_feat, W_pool1, b_pool1, dP);
    pool_kernel<<<POOLB, 256>>>(dP, dPl);
    gemm_out_kernel<64, 1><<<GEMMB, 256>>>(in_feat, dPl, W_self1, W_neigh1, bias1, dH);

    // ---- layer 2 ----
    gemm_pool_kernel<<<GEMMB, 256>>>(dH, W_pool2, b_pool2, dP);
    pool_kernel<<<POOLB, 256>>>(dP, dPl);
    gemm_out_kernel<16, 0><<<GEMMB, 256>>>(dH, dPl, W_self2, W_neigh2, bias2, out);
}

// round 2
// speedup vs baseline: 1.1683x; 1.1683x over previous
#include <cuda_runtime.h>
#include <cuda_fp16.h>
#include <cuda_bf16.h>

#define N_NODES 100000
#define N_EDGES 1600000
#define F 64
#define NCLS 16
#define NEG_SLOPE 0.01f

#define SCAN_BLK 1024
#define SCAN_NB ((N_NODES + SCAN_BLK - 1) / SCAN_BLK)   // 98

typedef unsigned long long ull;

// ---------------- scratch (device globals; no runtime allocation) ------------
__device__ int    g_off[N_NODES + 1];
__device__ int    g_cursor[N_NODES];
__device__ int    g_csr[N_EDGES];
__device__ int    g_bsum[SCAN_NB];
__device__ __half g_P[(size_t)N_NODES * F];       // fp16 messages
__device__ float  g_pooled[(size_t)N_NODES * F];
__device__ float  g_H[(size_t)N_NODES * F];

// ---------------- f32x2 helpers (sm_100+ packed fp32 FMA) --------------------
__device__ __forceinline__ void ffma2(ull& d, ull a, ull b) {
    asm("fma.rn.f32x2 %0, %1, %2, %0;" : "+l"(d) : "l"(a), "l"(b));
}
__device__ __forceinline__ ull pack2(float x) {
    ull r; asm("mov.b64 %0, {%1, %1};" : "=l"(r) : "f"(x)); return r;
}
__device__ __forceinline__ float2 unpack2(ull a) {
    float2 r; asm("mov.b64 {%0, %1}, %2;" : "=f"(r.x), "=f"(r.y) : "l"(a)); return r;
}

// ---------------- CSR build --------------------------------------------------
__global__ void zero_deg_kernel() {
    int i = blockIdx.x * blockDim.x + threadIdx.x;
    if (i <= N_NODES) g_off[i] = 0;
}

__global__ void hist_kernel(const int* __restrict__ dst) {
    int e = blockIdx.x * blockDim.x + threadIdx.x;
    if (e < N_EDGES) atomicAdd(&g_off[dst[e]], 1);
}

__global__ __launch_bounds__(SCAN_BLK) void scan1_kernel() {
    __shared__ int s[SCAN_BLK];
    int t = threadIdx.x;
    int idx = blockIdx.x * SCAN_BLK + t;
    int val = (idx < N_NODES) ? g_off[idx] : 0;
    s[t] = val;
    __syncthreads();
    #pragma unroll
    for (int o = 1; o < SCAN_BLK; o <<= 1) {
        int x = (t >= o) ? s[t - o] : 0;
        __syncthreads();
        s[t] += x;
        __syncthreads();
    }
    if (idx < N_NODES) g_off[idx] = s[t] - val;   // exclusive within scan-block
    if (t == SCAN_BLK - 1) g_bsum[blockIdx.x] = s[t];
}

// scan3: add block-sum prefix (computed cooperatively per block), init cursors
__global__ __launch_bounds__(256) void scan3_kernel() {
    __shared__ int sb[SCAN_NB];
    __shared__ int s_carry;
    int t = threadIdx.x;
    if (t < SCAN_NB) sb[t] = g_bsum[t];
    __syncthreads();
    if (t == 0) {
        int myblk = (blockIdx.x * 256) / SCAN_BLK;
        int c = 0;
        for (int i = 0; i < myblk; i++) c += sb[i];
        s_carry = c;
    }
    __syncthreads();
    int i = blockIdx.x * 256 + t;
    if (i < N_NODES) {
        int o = g_off[i] + s_carry;
        g_off[i] = o;
        g_cursor[i] = o;
    }
    if (i == 0) g_off[N_NODES] = N_EDGES;
}

__global__ void fill_csr_kernel(const int* __restrict__ src,
                                const int* __restrict__ dst) {
    int e = blockIdx.x * blockDim.x + threadIdx.x;
    if (e < N_EDGES) {
        int pos = atomicAdd(&g_cursor[dst[e]], 1);
        g_csr[pos] = src[e];
    }
}

// -------- GEMM: P[N,64] = relu(X[N,64] @ W[64,64] + b), fp16 output ----------
__global__ __launch_bounds__(256) void gemm_pool_kernel(
        const float* __restrict__ X, const float* __restrict__ W,
        const float* __restrict__ b, __half* __restrict__ Y) {
    __shared__ ulonglong2 sW[F * F / 4];   // [k][j4]: 2x f32x2 pairs (16 KB)
    __shared__ ull sb[F / 2];
    int t = threadIdx.x;
    const ulonglong2* W2 = (const ulonglong2*)W;
    #pragma unroll
    for (int i = 0; i < F * F / 4; i += 256) sW[i + t] = W2[i + t];
    if (t < F / 2) sb[t] = ((const ull*)b)[t];
    __syncthreads();

    int r = blockIdx.x * 256 + t;
    if (r >= N_NODES) return;

    ull acc[F / 2];
    #pragma unroll
    for (int j = 0; j < F / 2; j++) acc[j] = sb[j];

    const float4* xr = (const float4*)(X + (size_t)r * F);
    #pragma unroll
    for (int k4 = 0; k4 < F / 4; k4++) {
        float4 xv = __ldg(&xr[k4]);
        float xs[4] = {xv.x, xv.y, xv.z, xv.w};
        #pragma unroll
        for (int kk = 0; kk < 4; kk++) {
            int k = k4 * 4 + kk;
            ull xk = pack2(xs[kk]);
            #pragma unroll
            for (int j4 = 0; j4 < F / 4; j4++) {
                ulonglong2 w = sW[k * (F / 4) + j4];
                ffma2(acc[2 * j4 + 0], xk, w.x);
                ffma2(acc[2 * j4 + 1], xk, w.y);
            }
        }
    }
    // relu -> fp16, store as uint4 (8 x STG.128 per row)
    uint4* yr = (uint4*)(Y + (size_t)r * F);
    #pragma unroll
    for (int j8 = 0; j8 < F / 8; j8++) {
        unsigned u[4];
        #pragma unroll
        for (int q = 0; q < 4; q++) {
            float2 v = unpack2(acc[j8 * 4 + q]);
            __half2 h = __floats2half2_rn(fmaxf(v.x, 0.f), fmaxf(v.y, 0.f));
            u[q] = *reinterpret_cast<unsigned*>(&h);
        }
        uint4 o; o.x = u[0]; o.y = u[1]; o.z = u[2]; o.w = u[3];
        yr[j8] = o;
    }
}

// ---------------- segment max pool: warp per dst node, fp16 gather -----------
__global__ __launch_bounds__(256) void pool_kernel(const __half* __restrict__ P,
                                                   float* __restrict__ Pl) {
    int gwarp = (blockIdx.x * 256 + threadIdx.x) >> 5;
    int lane  = threadIdx.x & 31;
    if (gwarp >= N_NODES) return;
    const __half2* P2 = (const __half2*)P;
    int s0 = g_off[gwarp];
    int s1 = g_off[gwarp + 1];
    __half2 m = __float2half2_rn(0.f);
    int e = s0;
    for (; e + 4 <= s1; e += 4) {
        int i0 = g_csr[e + 0], i1 = g_csr[e + 1];
        int i2 = g_csr[e + 2], i3 = g_csr[e + 3];
        __half2 a0 = __ldg(&P2[i0 * (F / 2) + lane]);
        __half2 a1 = __ldg(&P2[i1 * (F / 2) + lane]);
        __half2 a2 = __ldg(&P2[i2 * (F / 2) + lane]);
        __half2 a3 = __ldg(&P2[i3 * (F / 2) + lane]);
        m = __hmax2(m, __hmax2(__hmax2(a0, a1), __hmax2(a2, a3)));
    }
    for (; e < s1; e++) {
        int i = g_csr[e];
        m = __hmax2(m, __ldg(&P2[i * (F / 2) + lane]));
    }
    float2 f = __half22float2(m);
    ((float2*)Pl)[gwarp * (F / 2) + lane] = f;
}

// ------- GEMM: Y[N,DOUT] = act(X@Ws + PL@Wn + b), K=64 each ------------------
// ACT: 0 = none, 1 = leaky_relu
template <int DOUT, int ACT>
__global__ __launch_bounds__(256) void gemm_out_kernel(
        const float* __restrict__ X, const float* __restrict__ PL,
        const float* __restrict__ Ws, const float* __restrict__ Wn,
        const float* __restrict__ b, float* __restrict__ Y) {
    __shared__ ulonglong2 sWs[F * DOUT / 4];
    __shared__ ulonglong2 sWn[F * DOUT / 4];
    __shared__ ull sb[DOUT / 2];
    int t = threadIdx.x;
    const ulonglong2* Ws2 = (const ulonglong2*)Ws;
    const ulonglong2* Wn2 = (const ulonglong2*)Wn;
    for (int i = t; i < F * DOUT / 4; i += 256) { sWs[i] = Ws2[i]; sWn[i] = Wn2[i]; }
    if (t < DOUT / 2) sb[t] = ((const ull*)b)[t];
    __syncthreads();

    int r = blockIdx.x * 256 + t;
    if (r >= N_NODES) return;

    ull acc[DOUT / 2];
    #pragma unroll
    for (int j = 0; j < DOUT / 2; j++) acc[j] = sb[j];

    const float4* xr = (const float4*)(X + (size_t)r * F);
    #pragma unroll
    for (int k4 = 0; k4 < F / 4; k4++) {
        float4 xv = __ldg(&xr[k4]);
        float xs[4] = {xv.x, xv.y, xv.z, xv.w};
        #pragma unroll
        for (int kk = 0; kk < 4; kk++) {
            int k = k4 * 4 + kk;
            ull xk = pack2(xs[kk]);
            #pragma unroll
            for (int j4 = 0; j4 < DOUT / 4; j4++) {
                ulonglong2 w = sWs[k * (DOUT / 4) + j4];
                ffma2(acc[2 * j4 + 0], xk, w.x);
                ffma2(acc[2 * j4 + 1], xk, w.y);
            }
        }
    }
    const float4* pr = (const float4*)(PL + (size_t)r * F);
    #pragma unroll
    for (int k4 = 0; k4 < F / 4; k4++) {
        float4 xv = __ldg(&pr[k4]);
        float xs[4] = {xv.x, xv.y, xv.z, xv.w};
        #pragma unroll
        for (int kk = 0; kk < 4; kk++) {
            int k = k4 * 4 + kk;
            ull xk = pack2(xs[kk]);
            #pragma unroll
            for (int j4 = 0; j4 < DOUT / 4; j4++) {
                ulonglong2 w = sWn[k * (DOUT / 4) + j4];
                ffma2(acc[2 * j4 + 0], xk, w.x);
                ffma2(acc[2 * j4 + 1], xk, w.y);
            }
        }
    }
    float4* yr = (float4*)(Y + (size_t)r * DOUT);
    #pragma unroll
    for (int j4 = 0; j4 < DOUT / 4; j4++) {
        float2 v0 = unpack2(acc[2 * j4 + 0]);
        float2 v1 = unpack2(acc[2 * j4 + 1]);
        float a0 = v0.x, a1 = v0.y, a2 = v1.x, a3 = v1.y;
        if (ACT == 1) {
            a0 = (a0 >= 0.f) ? a0 : NEG_SLOPE * a0;
            a1 = (a1 >= 0.f) ? a1 : NEG_SLOPE * a1;
            a2 = (a2 >= 0.f) ? a2 : NEG_SLOPE * a2;
            a3 = (a3 >= 0.f) ? a3 : NEG_SLOPE * a3;
        }
        float4 o; o.x = a0; o.y = a1; o.z = a2; o.w = a3;
        yr[j4] = o;
    }
}

// ---------------- launch -----------------------------------------------------
extern "C" void kernel_launch(void* const* d_in, const int* in_sizes, int n_in,
                              void* d_out, int out_size) {
    const float* in_feat = (const float*)d_in[0];
    const int*   src     = (const int*)d_in[1];
    const int*   dst     = (const int*)d_in[2];
    const float* W_pool1 = (const float*)d_in[3];
    const float* b_pool1 = (const float*)d_in[4];
    const float* W_self1 = (const float*)d_in[5];
    const float* W_neigh1= (const float*)d_in[6];
    const float* bias1   = (const float*)d_in[7];
    const float* W_pool2 = (const float*)d_in[8];
    const float* b_pool2 = (const float*)d_in[9];
    const float* W_self2 = (const float*)d_in[10];
    const float* W_neigh2= (const float*)d_in[11];
    const float* bias2   = (const float*)d_in[12];
    float* out = (float*)d_out;

    __half *dP; float *dPl, *dH;
    cudaGetSymbolAddress((void**)&dP, g_P);
    cudaGetSymbolAddress((void**)&dPl, g_pooled);
    cudaGetSymbolAddress((void**)&dH, g_H);

    const int EB    = (N_EDGES + 255) / 256;
    const int NB256 = (N_NODES + 255) / 256;
    const int POOLB = (N_NODES * 32 + 255) / 256;

    // ---- CSR build ----
    zero_deg_kernel<<<(N_NODES + 1 + 255) / 256, 256>>>();
    hist_kernel<<<EB, 256>>>(dst);
    scan1_kernel<<<SCAN_NB, SCAN_BLK>>>();
    scan3_kernel<<<NB256, 256>>>();
    fill_csr_kernel<<<EB, 256>>>(src, dst);

    // ---- layer 1 ----
    gemm_pool_kernel<<<NB256, 256>>>(in_feat, W_pool1, b_pool1, dP);
    pool_kernel<<<POOLB, 256>>>(dP, dPl);
    gemm_out_kernel<64, 1><<<NB256, 256>>>(in_feat, dPl, W_self1, W_neigh1, bias1, dH);

    // ---- layer 2 ----
    gemm_pool_kernel<<<NB256, 256>>>(dH, W_pool2, b_pool2, dP);
    pool_kernel<<<POOLB, 256>>>(dP, dPl);
    gemm_out_kernel<16, 0><<<NB256, 256>>>(dH, dPl, W_self2, W_neigh2, bias2, out);
}